// round 3
// baseline (speedup 1.0000x reference)
#include <cuda_runtime.h>
#include <math.h>

// Problem constants (fixed by the dataset)
#define NN 64
#define PP 17
#define HH 192
#define WW 192
#define NP (NN * PP)   // 1088 work items

__global__ __launch_bounds__(128)
void taylor_kernel(const float* __restrict__ coords,
                   const float* __restrict__ hm,
                   float* __restrict__ out)
{
    int i = blockIdx.x * blockDim.x + threadIdx.x;
    if (i >= NP) return;

    // coords[i] = (cx, cy) normalized; dims = [W, H]
    float cx = coords[2 * i + 0];
    float cy = coords[2 * i + 1];
    float xf = cx * (float)WW;
    float yf = cy * (float)HH;

    // int() truncation (coords >= 0 so trunc == floor)
    int px = (int)xf;
    int py = (int)yf;

    bool inb = (px > 1) && (px < WW - 2) && (py > 1) && (py < HH - 2);

    int pxc = min(max(px, 2), WW - 3);
    int pyc = min(max(py, 2), HH - 3);

    const float* base = hm + (size_t)i * (HH * WW) + (size_t)pyc * WW + pxc;

    // g(dy,dx) = log(h == 0 ? 1e-10 : h)
    #define G(dy, dx) ({ float v_ = base[(dy) * WW + (dx)]; \
                         __logf(0.0f); /* placeholder removed below */ v_; })
    // (macro trick above not used; use a lambda-style inline instead)

    auto ldlog = [&](int dy, int dx) -> float {
        float v = base[dy * WW + dx];
        return logf(v == 0.0f ? 1e-10f : v);
    };

    float g00   = ldlog( 0,  0);
    float gxp1  = ldlog( 0,  1);
    float gxm1  = ldlog( 0, -1);
    float gyp1  = ldlog( 1,  0);
    float gym1  = ldlog(-1,  0);
    float gxp2  = ldlog( 0,  2);
    float gxm2  = ldlog( 0, -2);
    float gyp2  = ldlog( 2,  0);
    float gym2  = ldlog(-2,  0);
    float gpp   = ldlog( 1,  1);
    float gmp   = ldlog(-1,  1);
    float gpm   = ldlog( 1, -1);
    float gmm   = ldlog(-1, -1);

    float dx  = 0.5f  * (gxp1 - gxm1);
    float dy  = 0.5f  * (gyp1 - gym1);
    float dxx = 0.25f * (gxp2 - 2.0f * g00 + gxm2);
    float dxy = 0.25f * (gpp - gmp - gpm + gmm);
    float dyy = 0.25f * (gyp2 - 2.0f * g00 + gym2);

    float det = dxx * dyy - dxy * dxy;
    bool ok = inb && (det != 0.0f);

    if (ok) {
        float inv = 1.0f / det;
        float offx = -(dyy * dx - dxy * dy) * inv;
        float offy = -(dxx * dy - dxy * dx) * inv;
        xf += offx;
        yf += offy;
    }

    // flip=True: output order is (y, x), back in normalized coords
    out[2 * i + 0] = yf / (float)HH;
    out[2 * i + 1] = xf / (float)WW;
}

extern "C" void kernel_launch(void* const* d_in, const int* in_sizes, int n_in,
                              void* d_out, int out_size)
{
    const float* coords = (const float*)d_in[0];
    const float* hm     = (const float*)d_in[1];
    float* out          = (float*)d_out;

    (void)in_sizes; (void)n_in; (void)out_size;

    taylor_kernel<<<(NP + 127) / 128, 128>>>(coords, hm, out);
}